// round 1
// baseline (speedup 1.0000x reference)
#include <cuda_runtime.h>
#include <math.h>

// Net_R1L: single-layer ReLU RNN, B=4096, T=2048, NIN=3, NHID=5, NOUT=1
// out[b] = tanh( W_out @ h_T + b_out ),  h_t = relu(x_t W_ih^T + b_ih + h_{t-1} W_hh^T + b_hh)
//
// Strategy: 1 thread per batch element (4096 threads = 128 warps, 1 warp/SM on
// 128 SMs -> 1 warp per SMSP, zero issue contention). The sequential chain is
// issue-bound on the fma pipe, so we halve fma-pipe ops with packed f32x2 FMAs
// (fma.rn.f32x2 — only reachable via inline PTX on sm_103a). Hidden dim 5 is
// packed as j-pairs (0,1),(2,3),(4,scalar): 24 fma-pipe ops per step for 40 MACs.
// ReLU (FMNMX) and the h/x duplication packs (MOV) go to the alu pipe, which has
// free issue slots under the 48-cycle fma-pipe window.
// x is streamed as float4 (8-step = 96B tiles, 16B aligned) with 1-tile prefetch.

#define TT 2048
#define NINPUT 3
#define NH 5

typedef unsigned long long u64;

static __device__ __forceinline__ u64 pack2(float lo, float hi) {
    u64 r;
    asm("mov.b64 %0, {%1, %2};" : "=l"(r) : "f"(lo), "f"(hi));
    return r;
}
static __device__ __forceinline__ void unpack2(u64 v, float& lo, float& hi) {
    asm("mov.b64 {%0, %1}, %2;" : "=f"(lo), "=f"(hi) : "l"(v));
}
static __device__ __forceinline__ u64 ffma2(u64 a, u64 b, u64 c) {
    u64 d;
    asm("fma.rn.f32x2 %0, %1, %2, %3;" : "=l"(d) : "l"(a), "l"(b), "l"(c));
    return d;
}

__global__ void __launch_bounds__(32, 1) rnn_relu_kernel(
    const float* __restrict__ state,   // [B, T, 3]
    const float* __restrict__ W_ih,    // [5, 3]
    const float* __restrict__ W_hh,    // [5, 5]
    const float* __restrict__ b_ih,    // [5]
    const float* __restrict__ b_hh,    // [5]
    const float* __restrict__ W_out,   // [1, 5]
    const float* __restrict__ b_out,   // [1]
    float* __restrict__ out,           // [B, 1]
    int B)
{
    const int b = blockIdx.x * 32 + threadIdx.x;
    if (b >= B) return;

    // ---- Load and pack weights (uniform across threads, L1/const-cached) ----
    // Combined bias c[j] = b_ih[j] + b_hh[j]
    float wih_s[NH][NINPUT];
    float whh_s[NH][NH];
    float c_s[NH];
#pragma unroll
    for (int j = 0; j < NH; j++) {
#pragma unroll
        for (int i = 0; i < NINPUT; i++) wih_s[j][i] = __ldg(&W_ih[j * NINPUT + i]);
#pragma unroll
        for (int k = 0; k < NH; k++) whh_s[j][k] = __ldg(&W_hh[j * NH + k]);
        c_s[j] = __ldg(&b_ih[j]) + __ldg(&b_hh[j]);
    }

    // j-pair packed weights: (j0,j1), (j2,j3), j4 scalar
    u64 wih01[NINPUT], wih23[NINPUT];
    float wih4[NINPUT];
#pragma unroll
    for (int i = 0; i < NINPUT; i++) {
        wih01[i] = pack2(wih_s[0][i], wih_s[1][i]);
        wih23[i] = pack2(wih_s[2][i], wih_s[3][i]);
        wih4[i]  = wih_s[4][i];
    }
    u64 whh01[NH], whh23[NH];
    float whh4[NH];
#pragma unroll
    for (int k = 0; k < NH; k++) {
        whh01[k] = pack2(whh_s[0][k], whh_s[1][k]);
        whh23[k] = pack2(whh_s[2][k], whh_s[3][k]);
        whh4[k]  = whh_s[4][k];
    }
    const u64   c01 = pack2(c_s[0], c_s[1]);
    const u64   c23 = pack2(c_s[2], c_s[3]);
    const float c4  = c_s[4];

    // ---- Hidden state ----
    float h[NH];
#pragma unroll
    for (int k = 0; k < NH; k++) h[k] = 0.0f;

    // ---- Stream x: this thread's row is contiguous 24KB. 8 steps = 24 floats
    //      = 6 float4 (96B, 16B-aligned). Double-buffer one tile ahead. ----
    const float4* __restrict__ xr =
        (const float4*)(state + (size_t)b * (size_t)(TT * NINPUT));
    const int NTILES = TT / 8;  // 256

    float4 buf[6];
#pragma unroll
    for (int i = 0; i < 6; i++) buf[i] = xr[i];

    for (int tile = 0; tile < NTILES; ++tile) {
        float4 cur[6];
#pragma unroll
        for (int i = 0; i < 6; i++) cur[i] = buf[i];

        // Prefetch next tile (clamped on last tile; re-reads valid memory).
        const int nt = (tile + 1 < NTILES) ? (tile + 1) : tile;
#pragma unroll
        for (int i = 0; i < 6; i++) buf[i] = xr[(size_t)nt * 6 + i];

        float xs[24];
#pragma unroll
        for (int i = 0; i < 6; i++) {
            xs[4 * i + 0] = cur[i].x;
            xs[4 * i + 1] = cur[i].y;
            xs[4 * i + 2] = cur[i].z;
            xs[4 * i + 3] = cur[i].w;
        }

#pragma unroll
        for (int s = 0; s < 8; ++s) {
            const float x0 = xs[s * 3 + 0];
            const float x1 = xs[s * 3 + 1];
            const float x2 = xs[s * 3 + 2];

            // x-proj: acc = c + x W_ih^T   (9 fma-pipe ops, 3 packs on alu pipe)
            const u64 xd0 = pack2(x0, x0);
            const u64 xd1 = pack2(x1, x1);
            const u64 xd2 = pack2(x2, x2);

            u64 a01 = ffma2(xd0, wih01[0], c01);
            u64 a23 = ffma2(xd0, wih23[0], c23);
            float a4 = fmaf(x0, wih4[0], c4);
            a01 = ffma2(xd1, wih01[1], a01);
            a23 = ffma2(xd1, wih23[1], a23);
            a4  = fmaf(x1, wih4[1], a4);
            a01 = ffma2(xd2, wih01[2], a01);
            a23 = ffma2(xd2, wih23[2], a23);
            a4  = fmaf(x2, wih4[2], a4);

            // recurrent: acc += h W_hh^T  (15 fma-pipe ops, 5 packs on alu pipe)
#pragma unroll
            for (int k = 0; k < NH; k++) {
                const u64 hd = pack2(h[k], h[k]);
                a01 = ffma2(hd, whh01[k], a01);
                a23 = ffma2(hd, whh23[k], a23);
                a4  = fmaf(h[k], whh4[k], a4);
            }

            // ReLU (FMNMX, alu pipe)
            float p0, p1, p2, p3;
            unpack2(a01, p0, p1);
            unpack2(a23, p2, p3);
            h[0] = fmaxf(p0, 0.0f);
            h[1] = fmaxf(p1, 0.0f);
            h[2] = fmaxf(p2, 0.0f);
            h[3] = fmaxf(p3, 0.0f);
            h[4] = fmaxf(a4, 0.0f);
        }
    }

    // ---- Readout: tanh(W_out @ h_T + b_out) ----
    float o = __ldg(&b_out[0]);
#pragma unroll
    for (int k = 0; k < NH; k++) o = fmaf(h[k], __ldg(&W_out[k]), o);
    out[b] = tanhf(o);
}

extern "C" void kernel_launch(void* const* d_in, const int* in_sizes, int n_in,
                              void* d_out, int out_size)
{
    const float* state = (const float*)d_in[0];
    const float* W_ih  = (const float*)d_in[1];
    const float* W_hh  = (const float*)d_in[2];
    const float* b_ih  = (const float*)d_in[3];
    const float* b_hh  = (const float*)d_in[4];
    const float* W_out = (const float*)d_in[5];
    const float* b_out = (const float*)d_in[6];
    float* out = (float*)d_out;

    const int B = in_sizes[0] / (TT * NINPUT);  // 4096
    const int threads = 32;
    const int blocks = (B + threads - 1) / threads;  // 128

    rnn_relu_kernel<<<blocks, threads>>>(state, W_ih, W_hh, b_ih, b_hh,
                                         W_out, b_out, out, B);
}